// round 16
// baseline (speedup 1.0000x reference)
#include <cuda_runtime.h>
#include <cuda_fp16.h>
#include <stdint.h>

#define BB 2
#define SS 2048
#define DD 1024
#define HH 16
#define NR (BB*SS)            // 4096 rows
#define ATT_SCALE 0.125f      // 1/sqrt(64)

// ---------------- device scratch (no cudaMalloc allowed) ----------------
static __device__ __half g_W3[3 * DD * DD];           // concat(Wq,Wk,Wv) fp16
static __device__ __half g_Wo[DD * DD];               // Wo fp16
static __device__ float  g_b3[3 * DD];
static __device__ __half g_X[(size_t)NR * DD];        // x fp16
static __device__ __half g_QKV[(size_t)NR * 3 * DD];  // (4096,3072) Q|K|V fp16
static __device__ __half g_VT[(size_t)32 * 64 * SS];  // V transposed: [z][d][s] fp16
static __device__ __half g_C[(size_t)NR * DD];        // ctx fp16
static __device__ __half g_P16[(size_t)32 * SS * SS]; // probs fp16 mirror for ctx

// ---------------- fp16 mma / ldmatrix / cp.async helpers ----------------
__device__ __forceinline__ void mma16(float* c, const uint32_t* a, const uint32_t* b) {
    asm volatile(
        "mma.sync.aligned.m16n8k16.row.col.f32.f16.f16.f32 "
        "{%0,%1,%2,%3},{%4,%5,%6,%7},{%8,%9},{%0,%1,%2,%3};"
        : "+f"(c[0]), "+f"(c[1]), "+f"(c[2]), "+f"(c[3])
        : "r"(a[0]), "r"(a[1]), "r"(a[2]), "r"(a[3]), "r"(b[0]), "r"(b[1]));
}
__device__ __forceinline__ void ldsm4(uint32_t& r0, uint32_t& r1, uint32_t& r2,
                                      uint32_t& r3, uint32_t addr) {
    asm volatile("ldmatrix.sync.aligned.m8n8.x4.shared.b16 {%0,%1,%2,%3}, [%4];"
                 : "=r"(r0), "=r"(r1), "=r"(r2), "=r"(r3) : "r"(addr));
}
__device__ __forceinline__ void cp16(void* dst, const void* src) {
    uint32_t d = (uint32_t)__cvta_generic_to_shared(dst);
    asm volatile("cp.async.cg.shared.global [%0], [%1], 16;" :: "r"(d), "l"(src));
}
__device__ __forceinline__ void cp_commit() { asm volatile("cp.async.commit_group;"); }
template <int N>
__device__ __forceinline__ void cp_wait() { asm volatile("cp.async.wait_group %0;" :: "n"(N)); }

// ---------------- prep: concat weights -> fp16; x -> fp16 ----------------
__global__ void concat_h(const float4* __restrict__ Wq, const float4* __restrict__ Wk,
                         const float4* __restrict__ Wv, const float4* __restrict__ Wo4,
                         const float* __restrict__ bq, const float* __restrict__ bk,
                         const float* __restrict__ bv) {
    const int i = blockIdx.x * 256 + threadIdx.x;   // float4 index, < DD*DD/4
    float4 a = Wq[i], b = Wk[i], c = Wv[i], d = Wo4[i];
    __half2* w3 = (__half2*)g_W3;
    __half2* wo = (__half2*)g_Wo;
    const int q2 = DD * DD / 2;
    w3[2*i]              = __floats2half2_rn(a.x, a.y);
    w3[2*i + 1]          = __floats2half2_rn(a.z, a.w);
    w3[q2 + 2*i]         = __floats2half2_rn(b.x, b.y);
    w3[q2 + 2*i + 1]     = __floats2half2_rn(b.z, b.w);
    w3[2*q2 + 2*i]       = __floats2half2_rn(c.x, c.y);
    w3[2*q2 + 2*i + 1]   = __floats2half2_rn(c.z, c.w);
    wo[2*i]              = __floats2half2_rn(d.x, d.y);
    wo[2*i + 1]          = __floats2half2_rn(d.z, d.w);
    if (i < DD) {
        g_b3[i]          = bq[i];
        g_b3[DD + i]     = bk[i];
        g_b3[2 * DD + i] = bv[i];
    }
}
__global__ void roundx_h(const float4* __restrict__ x) {
    const size_t i = (size_t)blockIdx.x * 256 + threadIdx.x;
    float4 v = x[i];
    __half2* X = (__half2*)g_X;
    X[2*i]     = __floats2half2_rn(v.x, v.y);
    X[2*i + 1] = __floats2half2_rn(v.z, v.w);
}

// ---------------- NT GEMM fp16: C = A @ B^T + bias; 128x128, BK=32, 4-stage ----
#define HSTG (128*40)   // halves per operand stage (stride 40 halves)
template <bool OUT_HALF>
__global__ __launch_bounds__(256, 2) void gemm_h(
    const __half* __restrict__ A, const __half* __restrict__ Bw,
    const float* __restrict__ bias, void* __restrict__ Cv,
    int M, int N, int K)
{
    extern __shared__ char smraw[];
    __half* As = (__half*)smraw;          // [4][128][40]
    __half* Bs = As + 4 * HSTG;           // [4][128][40]
    const uint32_t smem_u = (uint32_t)__cvta_generic_to_shared(smraw);
    const uint32_t bs_u   = smem_u + 4 * HSTG * 2;

    const int t = threadIdx.x, lane = t & 31, w = t >> 5;
    const int g = lane >> 2, tg = lane & 3;
    const int wm = w & 3, wn = w >> 2;
    const int row0 = blockIdx.y * 128, col0 = blockIdx.x * 128;

    const int li = lane >> 3, lj = lane & 7;
    uint32_t aoff[2], boff[4];
#pragma unroll
    for (int mt = 0; mt < 2; mt++)
        aoff[mt] = (uint32_t)(((wm * 32 + mt * 16 + (li & 1) * 8 + lj) * 40 + (li >> 1) * 8) * 2);
#pragma unroll
    for (int p = 0; p < 4; p++)
        boff[p] = (uint32_t)(((wn * 64 + p * 16 + (li >> 1) * 8 + lj) * 40 + (li & 1) * 8) * 2);

    const int lrow = t >> 1, lseg = (t & 1) * 16;
    const __half* Ap = A  + (size_t)(row0 + lrow) * K + lseg;
    const __half* Bp = Bw + (size_t)(col0 + lrow) * K + lseg;
    __half* Asd = As + lrow * 40 + lseg;
    __half* Bsd = Bs + lrow * 40 + lseg;

    float acc[2][8][4];
#pragma unroll
    for (int i = 0; i < 2; i++)
#pragma unroll
        for (int j = 0; j < 8; j++)
#pragma unroll
            for (int q = 0; q < 4; q++) acc[i][j][q] = 0.f;

    const int nk = K / 32;
#pragma unroll
    for (int s = 0; s < 3; s++) {
        cp16(Asd + s * HSTG, Ap + s * 32);
        cp16(Asd + s * HSTG + 8, Ap + s * 32 + 8);
        cp16(Bsd + s * HSTG, Bp + s * 32);
        cp16(Bsd + s * HSTG + 8, Bp + s * 32 + 8);
        cp_commit();
    }

    for (int kc = 0; kc < nk; kc++) {
        cp_wait<2>();
        __syncthreads();
        if (kc + 3 < nk) {
            const int s = (kc + 3) & 3;
            const int k0 = (kc + 3) * 32;
            cp16(Asd + s * HSTG, Ap + k0);
            cp16(Asd + s * HSTG + 8, Ap + k0 + 8);
            cp16(Bsd + s * HSTG, Bp + k0);
            cp16(Bsd + s * HSTG + 8, Bp + k0 + 8);
        }
        cp_commit();

        const uint32_t a_stage = smem_u + (uint32_t)((kc & 3) * HSTG * 2);
        const uint32_t b_stage = bs_u   + (uint32_t)((kc & 3) * HSTG * 2);
#pragma unroll
        for (int ks = 0; ks < 32; ks += 16) {
            uint32_t af[2][4], bf[8][2];
            ldsm4(af[0][0], af[0][1], af[0][2], af[0][3], a_stage + ks * 2 + aoff[0]);
            ldsm4(af[1][0], af[1][1], af[1][2], af[1][3], a_stage + ks * 2 + aoff[1]);
#pragma unroll
            for (int p = 0; p < 4; p++)
                ldsm4(bf[2*p][0], bf[2*p][1], bf[2*p+1][0], bf[2*p+1][1],
                      b_stage + ks * 2 + boff[p]);
#pragma unroll
            for (int mt = 0; mt < 2; mt++)
#pragma unroll
                for (int nt = 0; nt < 8; nt++)
                    mma16(acc[mt][nt], af[mt], bf[nt]);
        }
    }

#pragma unroll
    for (int mt = 0; mt < 2; mt++) {
        const int r = row0 + wm * 32 + mt * 16 + g;
#pragma unroll
        for (int nt = 0; nt < 8; nt++) {
            const int cc = col0 + wn * 64 + nt * 8 + 2 * tg;
            const float b0 = bias[cc], b1 = bias[cc + 1];
            if (OUT_HALF) {
                __half* C = (__half*)Cv;
                *(__half2*)(C + (size_t)r * N + cc) =
                    __floats2half2_rn(acc[mt][nt][0] + b0, acc[mt][nt][1] + b1);
                *(__half2*)(C + (size_t)(r + 8) * N + cc) =
                    __floats2half2_rn(acc[mt][nt][2] + b0, acc[mt][nt][3] + b1);
            } else {
                float* C = (float*)Cv;
                float2 v0, v1;
                v0.x = acc[mt][nt][0] + b0; v0.y = acc[mt][nt][1] + b1;
                v1.x = acc[mt][nt][2] + b0; v1.y = acc[mt][nt][3] + b1;
                *(float2*)(C + (size_t)r * N + cc)       = v0;
                *(float2*)(C + (size_t)(r + 8) * N + cc) = v1;
            }
        }
    }
}

// ---------------- V transpose (vectorized gmem sides) ----------------
__global__ void transpose_v(const __half* __restrict__ QKV, __half* __restrict__ VT)
{
    __shared__ __half ts[64 * 66];
    const int st = blockIdx.x, z = blockIdx.y;
    const int b = z >> 4, h = z & 15;
    const int t = threadIdx.x;

    for (int i = t; i < 512; i += 256) {
        const int r = i >> 3, cseg = (i & 7) * 8;
        uint4 v = *(const uint4*)(QKV + ((size_t)(b * SS) + st * 64 + r) * 3072
                                  + 2 * DD + h * 64 + cseg);
        const __half* hv = (const __half*)&v;
#pragma unroll
        for (int j = 0; j < 8; j++) ts[(cseg + j) * 66 + r] = hv[j];
    }
    __syncthreads();
    for (int i = t; i < 512; i += 256) {
        const int d = i >> 3, sseg = (i & 7) * 8;
        uint4 v;
        __half* hv = (__half*)&v;
#pragma unroll
        for (int j = 0; j < 8; j++) hv[j] = ts[d * 66 + sseg + j];
        *(uint4*)(VT + ((size_t)z * 64 + d) * SS + st * 64 + sseg) = v;
    }
}

// ---------------- scores fp16: lower tiles mma; upper tiles zero-fill ----------
__global__ __launch_bounds__(256, 2) void scores_h(
    const __half* __restrict__ QKV, float* __restrict__ attn)
{
    const int kt = blockIdx.x, qt = blockIdx.y, z = blockIdx.z;
    const int t = threadIdx.x;

    if (kt > qt) {
        // zero-fill this strict-upper 128x128 tile (softmax no longer writes here)
        const int row = t >> 1, cb = (t & 1) * 64;
        float* p0 = attn + ((size_t)z * SS + qt * 128 + row) * SS + kt * 128 + cb;
        const float4 z4 = make_float4(0.f, 0.f, 0.f, 0.f);
#pragma unroll
        for (int j = 0; j < 16; j++) *(float4*)(p0 + j * 4) = z4;
        return;
    }

    const int b = z >> 4, h = z & 15;

    extern __shared__ char smraw[];
    __half* Qs = (__half*)smraw;      // [128][72]
    __half* Ks = Qs + 128 * 72;       // [128][72]
    const uint32_t smem_u = (uint32_t)__cvta_generic_to_shared(smraw);
    const uint32_t ks_u   = smem_u + 128 * 72 * 2;

    const int lane = t & 31, w = t >> 5;
    const int g = lane >> 2, tg = lane & 3;
    const int wm = w & 3, wn = w >> 2;

    const int li = lane >> 3, lj = lane & 7;
    uint32_t aoff[2], boff[4];
#pragma unroll
    for (int mt = 0; mt < 2; mt++)
        aoff[mt] = (uint32_t)(((wm * 32 + mt * 16 + (li & 1) * 8 + lj) * 72 + (li >> 1) * 8) * 2);
#pragma unroll
    for (int p = 0; p < 4; p++)
        boff[p] = (uint32_t)(((wn * 64 + p * 16 + (li >> 1) * 8 + lj) * 72 + (li & 1) * 8) * 2);

    const int lrow = t >> 1, off0 = (t & 1) * 16;
    const __half* Qp = QKV + ((size_t)(b * SS) + qt * 128 + lrow) * 3072 + h * 64;
    const __half* Kp = QKV + ((size_t)(b * SS) + kt * 128 + lrow) * 3072 + DD + h * 64;
    __half* Qsd = Qs + lrow * 72;
    __half* Ksd = Ks + lrow * 72;

    cp16(Qsd + off0, Qp + off0);       cp16(Qsd + off0 + 8, Qp + off0 + 8);
    cp16(Ksd + off0, Kp + off0);       cp16(Ksd + off0 + 8, Kp + off0 + 8);
    cp_commit();
    cp16(Qsd + 32 + off0, Qp + 32 + off0);  cp16(Qsd + 40 + off0, Qp + 40 + off0);
    cp16(Ksd + 32 + off0, Kp + 32 + off0);  cp16(Ksd + 40 + off0, Kp + 40 + off0);
    cp_commit();

    float acc[2][8][4];
#pragma unroll
    for (int i = 0; i < 2; i++)
#pragma unroll
        for (int j = 0; j < 8; j++)
#pragma unroll
            for (int q = 0; q < 4; q++) acc[i][j][q] = 0.f;

    cp_wait<1>();
    __syncthreads();

#pragma unroll
    for (int half_ = 0; half_ < 2; half_++) {
#pragma unroll
        for (int ks0 = 0; ks0 < 32; ks0 += 16) {
            const int ks = half_ * 32 + ks0;
            uint32_t af[2][4], bf[8][2];
            ldsm4(af[0][0], af[0][1], af[0][2], af[0][3], smem_u + ks * 2 + aoff[0]);
            ldsm4(af[1][0], af[1][1], af[1][2], af[1][3], smem_u + ks * 2 + aoff[1]);
#pragma unroll
            for (int p = 0; p < 4; p++)
                ldsm4(bf[2*p][0], bf[2*p][1], bf[2*p+1][0], bf[2*p+1][1],
                      ks_u + ks * 2 + boff[p]);
#pragma unroll
            for (int mt = 0; mt < 2; mt++)
#pragma unroll
                for (int nt = 0; nt < 8; nt++)
                    mma16(acc[mt][nt], af[mt], bf[nt]);
        }
        if (half_ == 0) {
            cp_wait<0>();
            __syncthreads();
        }
    }

#pragma unroll
    for (int mt = 0; mt < 2; mt++) {
        const int r = qt * 128 + wm * 32 + mt * 16 + g;
#pragma unroll
        for (int nt = 0; nt < 8; nt++) {
            const int cc = kt * 128 + wn * 64 + nt * 8 + 2 * tg;
            float2 v0, v1;
            v0.x = acc[mt][nt][0] * ATT_SCALE; v0.y = acc[mt][nt][1] * ATT_SCALE;
            v1.x = acc[mt][nt][2] * ATT_SCALE; v1.y = acc[mt][nt][3] * ATT_SCALE;
            *(float2*)(attn + ((size_t)z * SS + r) * SS + cc)     = v0;
            *(float2*)(attn + ((size_t)z * SS + r + 8) * SS + cc) = v1;
        }
    }
}

// ---------------- softmax: causal-limited fp32 + fp16 mirror writes ----------
__global__ __launch_bounds__(256) void softmax_v11(float* __restrict__ attn,
                                                   __half* __restrict__ p16)
{
    const size_t row = blockIdx.x;
    const int q = (int)(row & (SS - 1));
    float4* p = (float4*)(attn + row * (size_t)SS);
    const float* ps = (const float*)p;
    __half* o16 = p16 + row * (size_t)SS;
    const int t = threadIdx.x;
    const int ia = 4 * t, ib = 1024 + 4 * t;
    const float NEG = -1e30f;

    float4 va = make_float4(NEG, NEG, NEG, NEG);
    float4 vb = make_float4(NEG, NEG, NEG, NEG);
    if (ia + 3 <= q) va = p[t];
    else if (ia <= q) {
        va.x = ps[ia];
        if (ia + 1 <= q) va.y = ps[ia + 1];
        if (ia + 2 <= q) va.z = ps[ia + 2];
    }
    if (ib + 3 <= q) vb = p[t + 256];
    else if (ib <= q) {
        vb.x = ps[ib];
        if (ib + 1 <= q) vb.y = ps[ib + 1];
        if (ib + 2 <= q) vb.z = ps[ib + 2];
    }

    float m = fmaxf(fmaxf(fmaxf(va.x, va.y), fmaxf(va.z, va.w)),
                    fmaxf(fmaxf(vb.x, vb.y), fmaxf(vb.z, vb.w)));
#pragma unroll
    for (int o = 16; o > 0; o >>= 1) m = fmaxf(m, __shfl_xor_sync(0xffffffffu, m, o));
    __shared__ float redm[8];
    __shared__ float reds[8];
    if ((t & 31) == 0) redm[t >> 5] = m;
    __syncthreads();
    float bm = redm[0];
#pragma unroll
    for (int w = 1; w < 8; w++) bm = fmaxf(bm, redm[w]);

    va.x = __expf(va.x - bm); va.y = __expf(va.y - bm);
    va.z = __expf(va.z - bm); va.w = __expf(va.w - bm);
    vb.x = __expf(vb.x - bm); vb.y = __expf(vb.y - bm);
    vb.z = __expf(vb.z - bm); vb.w = __expf(vb.w - bm);

    float s = va.x + va.y + va.z + va.w + vb.x + vb.y + vb.z + vb.w;
#pragma unroll
    for (int o = 16; o > 0; o >>= 1) s += __shfl_xor_sync(0xffffffffu, s, o);
    if ((t & 31) == 0) reds[t >> 5] = s;
    __syncthreads();
    float tot = 0.f;
#pragma unroll
    for (int w = 0; w < 8; w++) tot += reds[w];
    const float inv = 1.0f / tot;

    va.x *= inv; va.y *= inv; va.z *= inv; va.w *= inv;
    vb.x *= inv; vb.y *= inv; vb.z *= inv; vb.w *= inv;

    // writes limited to the diagonal tile's end; columns beyond are
    // zero-filled by scores_h's upper-triangle blocks
    const int lim = q | 127;
    if (ia <= lim) {
        p[t] = va;
        uint2 wa;
        ((__half2*)&wa)[0] = __floats2half2_rn(va.x, va.y);
        ((__half2*)&wa)[1] = __floats2half2_rn(va.z, va.w);
        *(uint2*)(o16 + ia) = wa;
    }
    if (ib <= lim) {
        p[t + 256] = vb;
        uint2 wb;
        ((__half2*)&wb)[0] = __floats2half2_rn(vb.x, vb.y);
        ((__half2*)&wb)[1] = __floats2half2_rn(vb.z, vb.w);
        *(uint2*)(o16 + ib) = wb;
    }
}

// ---------------- ctx fp16: P fp16 from mirror, full-LDSM, 2-stage ----------
#define PSTH (128*72)   // halves per P stage
#define VST  (64*72)    // halves per V stage
__global__ __launch_bounds__(256, 2) void ctx_h(
    const __half* __restrict__ P16, const __half* __restrict__ VT,
    __half* __restrict__ Cout)
{
    extern __shared__ char smraw[];
    __half* Ps = (__half*)smraw;            // [2][128][72]
    __half* Vs = Ps + 2 * PSTH;             // [2][64][72]
    const uint32_t smem_u = (uint32_t)__cvta_generic_to_shared(smraw);
    const uint32_t vs_u   = smem_u + 2 * PSTH * 2;

    const int qt = 15 - blockIdx.x;         // longest first
    const int z = blockIdx.y;
    const int b = z >> 4, h = z & 15;
    const int t = threadIdx.x, lane = t & 31, w = t >> 5;
    const int g = lane >> 2, tg = lane & 3;
    const int wm = w & 3, wn = w >> 2;

    const int li = lane >> 3, lj = lane & 7;
    uint32_t aoff[2], boff[2];
#pragma unroll
    for (int mt = 0; mt < 2; mt++)
        aoff[mt] = (uint32_t)(((wm * 32 + mt * 16 + (li & 1) * 8 + lj) * 72 + (li >> 1) * 8) * 2);
#pragma unroll
    for (int p = 0; p < 2; p++)
        boff[p] = (uint32_t)(((wn * 32 + p * 16 + (li >> 1) * 8 + lj) * 72 + (li & 1) * 8) * 2);

    const int prow = t >> 1, pseg = (t & 1) * 32;
    const int vrow = t >> 2, vseg = (t & 3) * 16;
    const __half* Pp = P16 + ((size_t)z * SS + qt * 128 + prow) * SS + pseg;
    const __half* Vp = VT + ((size_t)z * 64 + vrow) * SS + vseg;
    __half* Psd = Ps + prow * 72 + pseg;
    __half* Vsd = Vs + vrow * 72 + vseg;

    const int cnt = 2 * qt + 2;

    float acc[2][4][4];
#pragma unroll
    for (int i = 0; i < 2; i++)
#pragma unroll
        for (int j = 0; j < 4; j++)
#pragma unroll
            for (int q = 0; q < 4; q++) acc[i][j][q] = 0.f;

#pragma unroll
    for (int j = 0; j < 4; j++) cp16(Psd + j * 8, Pp + j * 8);
    cp16(Vsd, Vp); cp16(Vsd + 8, Vp + 8);
    cp_commit();

    for (int kti = 0; kti < cnt; kti++) {
        if (kti + 1 < cnt) {
            const int st = (kti + 1) & 1;
#pragma unroll
            for (int j = 0; j < 4; j++)
                cp16(Psd + st * PSTH + j * 8, Pp + (kti + 1) * 64 + j * 8);
            cp16(Vsd + st * VST, Vp + (kti + 1) * 64);
            cp16(Vsd + st * VST + 8, Vp + (kti + 1) * 64 + 8);
        }
        cp_commit();
        cp_wait<1>();
        __syncthreads();

        const uint32_t pstage = smem_u + (uint32_t)((kti & 1) * PSTH * 2);
        const uint32_t vstage = vs_u   + (uint32_t)((kti & 1) * VST * 2);
#pragma unroll
        for (int ks = 0; ks < 64; ks += 16) {
            uint32_t af[2][4], bf[4][2];
            ldsm4(af[0][0], af[0][1], af[0][2], af[0][3], pstage + ks * 2 + aoff[0]);
            ldsm4(af[1][0], af[1][1], af[1][2], af[1][3], pstage + ks * 2 + aoff[1]);
            ldsm4(bf[0][0], bf[0][1], bf[1][0], bf[1][1], vstage + ks * 2 + boff[0]);
            ldsm4(bf[2][0], bf[2][1], bf[3][0], bf[3][1], vstage + ks * 2 + boff[1]);
#pragma unroll
            for (int mt = 0; mt < 2; mt++)
#pragma unroll
                for (int nt = 0; nt < 4; nt++)
                    mma16(acc[mt][nt], af[mt], bf[nt]);
        }
        __syncthreads();
    }

#pragma unroll
    for (int mt = 0; mt < 2; mt++) {
        const int qrow = qt * 128 + wm * 32 + mt * 16 + g;
#pragma unroll
        for (int nt = 0; nt < 4; nt++) {
            const int cc = h * 64 + wn * 32 + nt * 8 + 2 * tg;
            *(__half2*)(Cout + ((size_t)(b * SS) + qrow) * DD + cc) =
                __floats2half2_rn(acc[mt][nt][0], acc[mt][nt][1]);
            *(__half2*)(Cout + ((size_t)(b * SS) + qrow + 8) * DD + cc) =
                __floats2half2_rn(acc[mt][nt][2], acc[mt][nt][3]);
        }
    }
}

// ---------------- launch ----------------
extern "C" void kernel_launch(void* const* d_in, const int* in_sizes, int n_in,
                              void* d_out, int out_size)
{
    const float* x  = (const float*)d_in[0];
    const float* Wq = (const float*)d_in[1];
    const float* bq = (const float*)d_in[2];
    const float* Wk = (const float*)d_in[3];
    const float* bk = (const float*)d_in[4];
    const float* Wv = (const float*)d_in[5];
    const float* bv = (const float*)d_in[6];
    const float* Wo = (const float*)d_in[7];
    const float* bo = (const float*)d_in[8];

    float* out  = (float*)d_out;
    float* attn = out + (size_t)NR * DD;   // tuple order: (out, attn)

    __half *pW3, *pWo, *pX, *pQKV, *pVT, *pC, *pP16;
    float *pb3;
    cudaGetSymbolAddress((void**)&pW3,  g_W3);
    cudaGetSymbolAddress((void**)&pWo,  g_Wo);
    cudaGetSymbolAddress((void**)&pb3,  g_b3);
    cudaGetSymbolAddress((void**)&pX,   g_X);
    cudaGetSymbolAddress((void**)&pQKV, g_QKV);
    cudaGetSymbolAddress((void**)&pVT,  g_VT);
    cudaGetSymbolAddress((void**)&pC,   g_C);
    cudaGetSymbolAddress((void**)&pP16, g_P16);

    const int gemm_smem   = 4 * HSTG * 2 * 2;              // 81920 B
    const int scores_smem = 2 * 128 * 72 * 2;              // 36864 B
    const int ctx_smem    = (2 * PSTH + 2 * VST) * 2;      // 55296 B
    cudaFuncSetAttribute(gemm_h<true>,  cudaFuncAttributeMaxDynamicSharedMemorySize, gemm_smem);
    cudaFuncSetAttribute(gemm_h<false>, cudaFuncAttributeMaxDynamicSharedMemorySize, gemm_smem);
    cudaFuncSetAttribute(scores_h,      cudaFuncAttributeMaxDynamicSharedMemorySize, scores_smem);
    cudaFuncSetAttribute(ctx_h,         cudaFuncAttributeMaxDynamicSharedMemorySize, ctx_smem);

    // 1) prep
    concat_h<<<(DD * DD / 4) / 256, 256>>>(
        (const float4*)Wq, (const float4*)Wk, (const float4*)Wv, (const float4*)Wo,
        bq, bk, bv);
    roundx_h<<<((size_t)NR * DD / 4) / 256, 256>>>((const float4*)x);

    // 2) fused QKV projection -> fp16
    gemm_h<true><<<dim3(3072 / 128, NR / 128), 256, gemm_smem>>>(pX, pW3, pb3, pQKV, NR, 3072, DD);

    // 3) transpose V slice for ctx B-operand layout
    transpose_v<<<dim3(SS / 64, BB * HH), 256>>>(pQKV, pVT);

    // 4) raw causal scores (fp16 mma); upper-triangle tiles zero-filled here
    scores_h<<<dim3(SS / 128, SS / 128, BB * HH), 256, scores_smem>>>(pQKV, attn);

    // 5) softmax per row: causal-limited fp32 probs + fp16 mirror
    softmax_v11<<<BB * HH * SS, 256>>>(attn, pP16);

    // 6) ctx = attn @ V (fp16 mma, fp16 P, full-LDSM) -> fp16 ctx
    ctx_h<<<dim3(SS / 128, BB * HH), 256, ctx_smem>>>(pP16, pVT, pC);

    // 7) output projection (fp32 out)
    gemm_h<false><<<dim3(DD / 128, NR / 128), 256, gemm_smem>>>(pC, pWo, bo, out, NR, DD, DD);
}

// round 17
// speedup vs baseline: 1.0811x; 1.0811x over previous
#include <cuda_runtime.h>
#include <cuda_fp16.h>
#include <stdint.h>

#define BB 2
#define SS 2048
#define DD 1024
#define HH 16
#define NR (BB*SS)            // 4096 rows
#define ATT_SCALE 0.125f      // 1/sqrt(64)

// ---------------- device scratch (no cudaMalloc allowed) ----------------
static __device__ __half g_W3[3 * DD * DD];           // concat(Wq,Wk,Wv) fp16
static __device__ __half g_Wo[DD * DD];               // Wo fp16
static __device__ float  g_b3[3 * DD];
static __device__ __half g_X[(size_t)NR * DD];        // x fp16
static __device__ __half g_QKV[(size_t)NR * 3 * DD];  // (4096,3072) Q|K|V fp16
static __device__ __half g_VT[(size_t)32 * 64 * SS];  // V transposed: [z][d][s] fp16
static __device__ __half g_C[(size_t)NR * DD];        // ctx fp16
static __device__ __half g_P16[(size_t)32 * SS * SS]; // probs fp16 mirror for ctx

// ---------------- fp16 mma / ldmatrix / cp.async helpers ----------------
__device__ __forceinline__ void mma16(float* c, const uint32_t* a, const uint32_t* b) {
    asm volatile(
        "mma.sync.aligned.m16n8k16.row.col.f32.f16.f16.f32 "
        "{%0,%1,%2,%3},{%4,%5,%6,%7},{%8,%9},{%0,%1,%2,%3};"
        : "+f"(c[0]), "+f"(c[1]), "+f"(c[2]), "+f"(c[3])
        : "r"(a[0]), "r"(a[1]), "r"(a[2]), "r"(a[3]), "r"(b[0]), "r"(b[1]));
}
__device__ __forceinline__ void ldsm4(uint32_t& r0, uint32_t& r1, uint32_t& r2,
                                      uint32_t& r3, uint32_t addr) {
    asm volatile("ldmatrix.sync.aligned.m8n8.x4.shared.b16 {%0,%1,%2,%3}, [%4];"
                 : "=r"(r0), "=r"(r1), "=r"(r2), "=r"(r3) : "r"(addr));
}
__device__ __forceinline__ void cp16(void* dst, const void* src) {
    uint32_t d = (uint32_t)__cvta_generic_to_shared(dst);
    asm volatile("cp.async.cg.shared.global [%0], [%1], 16;" :: "r"(d), "l"(src));
}
__device__ __forceinline__ void cp_commit() { asm volatile("cp.async.commit_group;"); }
template <int N>
__device__ __forceinline__ void cp_wait() { asm volatile("cp.async.wait_group %0;" :: "n"(N)); }

// ---------------- prep: concat weights -> fp16; x -> fp16 ----------------
__global__ void concat_h(const float4* __restrict__ Wq, const float4* __restrict__ Wk,
                         const float4* __restrict__ Wv, const float4* __restrict__ Wo4,
                         const float* __restrict__ bq, const float* __restrict__ bk,
                         const float* __restrict__ bv) {
    const int i = blockIdx.x * 256 + threadIdx.x;   // float4 index, < DD*DD/4
    float4 a = Wq[i], b = Wk[i], c = Wv[i], d = Wo4[i];
    __half2* w3 = (__half2*)g_W3;
    __half2* wo = (__half2*)g_Wo;
    const int q2 = DD * DD / 2;
    w3[2*i]              = __floats2half2_rn(a.x, a.y);
    w3[2*i + 1]          = __floats2half2_rn(a.z, a.w);
    w3[q2 + 2*i]         = __floats2half2_rn(b.x, b.y);
    w3[q2 + 2*i + 1]     = __floats2half2_rn(b.z, b.w);
    w3[2*q2 + 2*i]       = __floats2half2_rn(c.x, c.y);
    w3[2*q2 + 2*i + 1]   = __floats2half2_rn(c.z, c.w);
    wo[2*i]              = __floats2half2_rn(d.x, d.y);
    wo[2*i + 1]          = __floats2half2_rn(d.z, d.w);
    if (i < DD) {
        g_b3[i]          = bq[i];
        g_b3[DD + i]     = bk[i];
        g_b3[2 * DD + i] = bv[i];
    }
}
__global__ void roundx_h(const float4* __restrict__ x) {
    const size_t i = (size_t)blockIdx.x * 256 + threadIdx.x;
    float4 v = x[i];
    __half2* X = (__half2*)g_X;
    X[2*i]     = __floats2half2_rn(v.x, v.y);
    X[2*i + 1] = __floats2half2_rn(v.z, v.w);
}

// ---------------- NT GEMM fp16: C = A @ B^T + bias; 128x128, BK=32, 4-stage ----
#define HSTG (128*40)   // halves per operand stage (stride 40 halves)
template <bool OUT_HALF>
__global__ __launch_bounds__(256, 2) void gemm_h(
    const __half* __restrict__ A, const __half* __restrict__ Bw,
    const float* __restrict__ bias, void* __restrict__ Cv,
    int M, int N, int K)
{
    extern __shared__ char smraw[];
    __half* As = (__half*)smraw;          // [4][128][40]
    __half* Bs = As + 4 * HSTG;           // [4][128][40]
    const uint32_t smem_u = (uint32_t)__cvta_generic_to_shared(smraw);
    const uint32_t bs_u   = smem_u + 4 * HSTG * 2;

    const int t = threadIdx.x, lane = t & 31, w = t >> 5;
    const int g = lane >> 2, tg = lane & 3;
    const int wm = w & 3, wn = w >> 2;
    const int row0 = blockIdx.y * 128, col0 = blockIdx.x * 128;

    const int li = lane >> 3, lj = lane & 7;
    uint32_t aoff[2], boff[4];
#pragma unroll
    for (int mt = 0; mt < 2; mt++)
        aoff[mt] = (uint32_t)(((wm * 32 + mt * 16 + (li & 1) * 8 + lj) * 40 + (li >> 1) * 8) * 2);
#pragma unroll
    for (int p = 0; p < 4; p++)
        boff[p] = (uint32_t)(((wn * 64 + p * 16 + (li >> 1) * 8 + lj) * 40 + (li & 1) * 8) * 2);

    const int lrow = t >> 1, lseg = (t & 1) * 16;
    const __half* Ap = A  + (size_t)(row0 + lrow) * K + lseg;
    const __half* Bp = Bw + (size_t)(col0 + lrow) * K + lseg;
    __half* Asd = As + lrow * 40 + lseg;
    __half* Bsd = Bs + lrow * 40 + lseg;

    float acc[2][8][4];
#pragma unroll
    for (int i = 0; i < 2; i++)
#pragma unroll
        for (int j = 0; j < 8; j++)
#pragma unroll
            for (int q = 0; q < 4; q++) acc[i][j][q] = 0.f;

    const int nk = K / 32;
#pragma unroll
    for (int s = 0; s < 3; s++) {
        cp16(Asd + s * HSTG, Ap + s * 32);
        cp16(Asd + s * HSTG + 8, Ap + s * 32 + 8);
        cp16(Bsd + s * HSTG, Bp + s * 32);
        cp16(Bsd + s * HSTG + 8, Bp + s * 32 + 8);
        cp_commit();
    }

    for (int kc = 0; kc < nk; kc++) {
        cp_wait<2>();
        __syncthreads();
        if (kc + 3 < nk) {
            const int s = (kc + 3) & 3;
            const int k0 = (kc + 3) * 32;
            cp16(Asd + s * HSTG, Ap + k0);
            cp16(Asd + s * HSTG + 8, Ap + k0 + 8);
            cp16(Bsd + s * HSTG, Bp + k0);
            cp16(Bsd + s * HSTG + 8, Bp + k0 + 8);
        }
        cp_commit();

        const uint32_t a_stage = smem_u + (uint32_t)((kc & 3) * HSTG * 2);
        const uint32_t b_stage = bs_u   + (uint32_t)((kc & 3) * HSTG * 2);
#pragma unroll
        for (int ks = 0; ks < 32; ks += 16) {
            uint32_t af[2][4], bf[8][2];
            ldsm4(af[0][0], af[0][1], af[0][2], af[0][3], a_stage + ks * 2 + aoff[0]);
            ldsm4(af[1][0], af[1][1], af[1][2], af[1][3], a_stage + ks * 2 + aoff[1]);
#pragma unroll
            for (int p = 0; p < 4; p++)
                ldsm4(bf[2*p][0], bf[2*p][1], bf[2*p+1][0], bf[2*p+1][1],
                      b_stage + ks * 2 + boff[p]);
#pragma unroll
            for (int mt = 0; mt < 2; mt++)
#pragma unroll
                for (int nt = 0; nt < 8; nt++)
                    mma16(acc[mt][nt], af[mt], bf[nt]);
        }
    }

#pragma unroll
    for (int mt = 0; mt < 2; mt++) {
        const int r = row0 + wm * 32 + mt * 16 + g;
#pragma unroll
        for (int nt = 0; nt < 8; nt++) {
            const int cc = col0 + wn * 64 + nt * 8 + 2 * tg;
            const float b0 = bias[cc], b1 = bias[cc + 1];
            if (OUT_HALF) {
                __half* C = (__half*)Cv;
                *(__half2*)(C + (size_t)r * N + cc) =
                    __floats2half2_rn(acc[mt][nt][0] + b0, acc[mt][nt][1] + b1);
                *(__half2*)(C + (size_t)(r + 8) * N + cc) =
                    __floats2half2_rn(acc[mt][nt][2] + b0, acc[mt][nt][3] + b1);
            } else {
                float* C = (float*)Cv;
                float2 v0, v1;
                v0.x = acc[mt][nt][0] + b0; v0.y = acc[mt][nt][1] + b1;
                v1.x = acc[mt][nt][2] + b0; v1.y = acc[mt][nt][3] + b1;
                *(float2*)(C + (size_t)r * N + cc)       = v0;
                *(float2*)(C + (size_t)(r + 8) * N + cc) = v1;
            }
        }
    }
}

// ---------------- V transpose (vectorized gmem sides) ----------------
__global__ void transpose_v(const __half* __restrict__ QKV, __half* __restrict__ VT)
{
    __shared__ __half ts[64 * 66];
    const int st = blockIdx.x, z = blockIdx.y;
    const int b = z >> 4, h = z & 15;
    const int t = threadIdx.x;

    for (int i = t; i < 512; i += 256) {
        const int r = i >> 3, cseg = (i & 7) * 8;
        uint4 v = *(const uint4*)(QKV + ((size_t)(b * SS) + st * 64 + r) * 3072
                                  + 2 * DD + h * 64 + cseg);
        const __half* hv = (const __half*)&v;
#pragma unroll
        for (int j = 0; j < 8; j++) ts[(cseg + j) * 66 + r] = hv[j];
    }
    __syncthreads();
    for (int i = t; i < 512; i += 256) {
        const int d = i >> 3, sseg = (i & 7) * 8;
        uint4 v;
        __half* hv = (__half*)&v;
#pragma unroll
        for (int j = 0; j < 8; j++) hv[j] = ts[d * 66 + sseg + j];
        *(uint4*)(VT + ((size_t)z * 64 + d) * SS + st * 64 + sseg) = v;
    }
}

// ---------------- scores fp16: 128x128 tiles, 2-phase cp.async, K=64 ----------
__global__ __launch_bounds__(256, 2) void scores_h(
    const __half* __restrict__ QKV, float* __restrict__ attn)
{
    const int kt = blockIdx.x, qt = blockIdx.y, z = blockIdx.z;
    if (kt > qt) return;
    const int b = z >> 4, h = z & 15;

    extern __shared__ char smraw[];
    __half* Qs = (__half*)smraw;      // [128][72]
    __half* Ks = Qs + 128 * 72;       // [128][72]
    const uint32_t smem_u = (uint32_t)__cvta_generic_to_shared(smraw);
    const uint32_t ks_u   = smem_u + 128 * 72 * 2;

    const int t = threadIdx.x, lane = t & 31, w = t >> 5;
    const int g = lane >> 2, tg = lane & 3;
    const int wm = w & 3, wn = w >> 2;

    const int li = lane >> 3, lj = lane & 7;
    uint32_t aoff[2], boff[4];
#pragma unroll
    for (int mt = 0; mt < 2; mt++)
        aoff[mt] = (uint32_t)(((wm * 32 + mt * 16 + (li & 1) * 8 + lj) * 72 + (li >> 1) * 8) * 2);
#pragma unroll
    for (int p = 0; p < 4; p++)
        boff[p] = (uint32_t)(((wn * 64 + p * 16 + (li >> 1) * 8 + lj) * 72 + (li & 1) * 8) * 2);

    const int lrow = t >> 1, off0 = (t & 1) * 16;
    const __half* Qp = QKV + ((size_t)(b * SS) + qt * 128 + lrow) * 3072 + h * 64;
    const __half* Kp = QKV + ((size_t)(b * SS) + kt * 128 + lrow) * 3072 + DD + h * 64;
    __half* Qsd = Qs + lrow * 72;
    __half* Ksd = Ks + lrow * 72;

    cp16(Qsd + off0, Qp + off0);       cp16(Qsd + off0 + 8, Qp + off0 + 8);
    cp16(Ksd + off0, Kp + off0);       cp16(Ksd + off0 + 8, Kp + off0 + 8);
    cp_commit();
    cp16(Qsd + 32 + off0, Qp + 32 + off0);  cp16(Qsd + 40 + off0, Qp + 40 + off0);
    cp16(Ksd + 32 + off0, Kp + 32 + off0);  cp16(Ksd + 40 + off0, Kp + 40 + off0);
    cp_commit();

    float acc[2][8][4];
#pragma unroll
    for (int i = 0; i < 2; i++)
#pragma unroll
        for (int j = 0; j < 8; j++)
#pragma unroll
            for (int q = 0; q < 4; q++) acc[i][j][q] = 0.f;

    cp_wait<1>();
    __syncthreads();

#pragma unroll
    for (int half_ = 0; half_ < 2; half_++) {
#pragma unroll
        for (int ks0 = 0; ks0 < 32; ks0 += 16) {
            const int ks = half_ * 32 + ks0;
            uint32_t af[2][4], bf[8][2];
            ldsm4(af[0][0], af[0][1], af[0][2], af[0][3], smem_u + ks * 2 + aoff[0]);
            ldsm4(af[1][0], af[1][1], af[1][2], af[1][3], smem_u + ks * 2 + aoff[1]);
#pragma unroll
            for (int p = 0; p < 4; p++)
                ldsm4(bf[2*p][0], bf[2*p][1], bf[2*p+1][0], bf[2*p+1][1],
                      ks_u + ks * 2 + boff[p]);
#pragma unroll
            for (int mt = 0; mt < 2; mt++)
#pragma unroll
                for (int nt = 0; nt < 8; nt++)
                    mma16(acc[mt][nt], af[mt], bf[nt]);
        }
        if (half_ == 0) {
            cp_wait<0>();
            __syncthreads();
        }
    }

#pragma unroll
    for (int mt = 0; mt < 2; mt++) {
        const int r = qt * 128 + wm * 32 + mt * 16 + g;
#pragma unroll
        for (int nt = 0; nt < 8; nt++) {
            const int cc = kt * 128 + wn * 64 + nt * 8 + 2 * tg;
            float2 v0, v1;
            v0.x = acc[mt][nt][0] * ATT_SCALE; v0.y = acc[mt][nt][1] * ATT_SCALE;
            v1.x = acc[mt][nt][2] * ATT_SCALE; v1.y = acc[mt][nt][3] * ATT_SCALE;
            *(float2*)(attn + ((size_t)z * SS + r) * SS + cc)     = v0;
            *(float2*)(attn + ((size_t)z * SS + r + 8) * SS + cc) = v1;
        }
    }
}

// ---------------- softmax: fp32 probs to attn + causal-limited fp16 mirror ----------
__global__ __launch_bounds__(256) void softmax_v10(float* __restrict__ attn,
                                                   __half* __restrict__ p16)
{
    const size_t row = blockIdx.x;
    const int q = (int)(row & (SS - 1));
    float4* p = (float4*)(attn + row * (size_t)SS);
    const float* ps = (const float*)p;
    __half* o16 = p16 + row * (size_t)SS;
    const int t = threadIdx.x;
    const int ia = 4 * t, ib = 1024 + 4 * t;
    const float NEG = -1e30f;

    float4 va = make_float4(NEG, NEG, NEG, NEG);
    float4 vb = make_float4(NEG, NEG, NEG, NEG);
    if (ia + 3 <= q) va = p[t];
    else if (ia <= q) {
        va.x = ps[ia];
        if (ia + 1 <= q) va.y = ps[ia + 1];
        if (ia + 2 <= q) va.z = ps[ia + 2];
    }
    if (ib + 3 <= q) vb = p[t + 256];
    else if (ib <= q) {
        vb.x = ps[ib];
        if (ib + 1 <= q) vb.y = ps[ib + 1];
        if (ib + 2 <= q) vb.z = ps[ib + 2];
    }

    float m = fmaxf(fmaxf(fmaxf(va.x, va.y), fmaxf(va.z, va.w)),
                    fmaxf(fmaxf(vb.x, vb.y), fmaxf(vb.z, vb.w)));
#pragma unroll
    for (int o = 16; o > 0; o >>= 1) m = fmaxf(m, __shfl_xor_sync(0xffffffffu, m, o));
    __shared__ float redm[8];
    __shared__ float reds[8];
    if ((t & 31) == 0) redm[t >> 5] = m;
    __syncthreads();
    float bm = redm[0];
#pragma unroll
    for (int w = 1; w < 8; w++) bm = fmaxf(bm, redm[w]);

    va.x = __expf(va.x - bm); va.y = __expf(va.y - bm);
    va.z = __expf(va.z - bm); va.w = __expf(va.w - bm);
    vb.x = __expf(vb.x - bm); vb.y = __expf(vb.y - bm);
    vb.z = __expf(vb.z - bm); vb.w = __expf(vb.w - bm);

    float s = va.x + va.y + va.z + va.w + vb.x + vb.y + vb.z + vb.w;
#pragma unroll
    for (int o = 16; o > 0; o >>= 1) s += __shfl_xor_sync(0xffffffffu, s, o);
    if ((t & 31) == 0) reds[t >> 5] = s;
    __syncthreads();
    float tot = 0.f;
#pragma unroll
    for (int w = 0; w < 8; w++) tot += reds[w];
    const float inv = 1.0f / tot;

    va.x *= inv; va.y *= inv; va.z *= inv; va.w *= inv;
    vb.x *= inv; vb.y *= inv; vb.z *= inv; vb.w *= inv;
    p[t] = va;
    p[t + 256] = vb;

    // fp16 mirror: ctx only reads columns <= (q | 127); skip the rest
    const int lim = q | 127;
    if (ia <= lim) {
        uint2 wa;
        ((__half2*)&wa)[0] = __floats2half2_rn(va.x, va.y);
        ((__half2*)&wa)[1] = __floats2half2_rn(va.z, va.w);
        *(uint2*)(o16 + ia) = wa;
    }
    if (ib <= lim) {
        uint2 wb;
        ((__half2*)&wb)[0] = __floats2half2_rn(vb.x, vb.y);
        ((__half2*)&wb)[1] = __floats2half2_rn(vb.z, vb.w);
        *(uint2*)(o16 + ib) = wb;
    }
}

// ---------------- ctx fp16: P fp16 from mirror, full-LDSM, 2-stage ----------
#define PSTH (128*72)   // halves per P stage
#define VST  (64*72)    // halves per V stage
__global__ __launch_bounds__(256, 2) void ctx_h(
    const __half* __restrict__ P16, const __half* __restrict__ VT,
    __half* __restrict__ Cout)
{
    extern __shared__ char smraw[];
    __half* Ps = (__half*)smraw;            // [2][128][72]
    __half* Vs = Ps + 2 * PSTH;             // [2][64][72]
    const uint32_t smem_u = (uint32_t)__cvta_generic_to_shared(smraw);
    const uint32_t vs_u   = smem_u + 2 * PSTH * 2;

    const int qt = 15 - blockIdx.x;         // longest first
    const int z = blockIdx.y;
    const int b = z >> 4, h = z & 15;
    const int t = threadIdx.x, lane = t & 31, w = t >> 5;
    const int g = lane >> 2, tg = lane & 3;
    const int wm = w & 3, wn = w >> 2;

    const int li = lane >> 3, lj = lane & 7;
    uint32_t aoff[2], boff[2];
#pragma unroll
    for (int mt = 0; mt < 2; mt++)
        aoff[mt] = (uint32_t)(((wm * 32 + mt * 16 + (li & 1) * 8 + lj) * 72 + (li >> 1) * 8) * 2);
#pragma unroll
    for (int p = 0; p < 2; p++)
        boff[p] = (uint32_t)(((wn * 32 + p * 16 + (li >> 1) * 8 + lj) * 72 + (li & 1) * 8) * 2);

    const int prow = t >> 1, pseg = (t & 1) * 32;
    const int vrow = t >> 2, vseg = (t & 3) * 16;
    const __half* Pp = P16 + ((size_t)z * SS + qt * 128 + prow) * SS + pseg;
    const __half* Vp = VT + ((size_t)z * 64 + vrow) * SS + vseg;
    __half* Psd = Ps + prow * 72 + pseg;
    __half* Vsd = Vs + vrow * 72 + vseg;

    const int cnt = 2 * qt + 2;

    float acc[2][4][4];
#pragma unroll
    for (int i = 0; i < 2; i++)
#pragma unroll
        for (int j = 0; j < 4; j++)
#pragma unroll
            for (int q = 0; q < 4; q++) acc[i][j][q] = 0.f;

#pragma unroll
    for (int j = 0; j < 4; j++) cp16(Psd + j * 8, Pp + j * 8);
    cp16(Vsd, Vp); cp16(Vsd + 8, Vp + 8);
    cp_commit();

    for (int kti = 0; kti < cnt; kti++) {
        if (kti + 1 < cnt) {
            const int st = (kti + 1) & 1;
#pragma unroll
            for (int j = 0; j < 4; j++)
                cp16(Psd + st * PSTH + j * 8, Pp + (kti + 1) * 64 + j * 8);
            cp16(Vsd + st * VST, Vp + (kti + 1) * 64);
            cp16(Vsd + st * VST + 8, Vp + (kti + 1) * 64 + 8);
        }
        cp_commit();
        cp_wait<1>();
        __syncthreads();

        const uint32_t pstage = smem_u + (uint32_t)((kti & 1) * PSTH * 2);
        const uint32_t vstage = vs_u   + (uint32_t)((kti & 1) * VST * 2);
#pragma unroll
        for (int ks = 0; ks < 64; ks += 16) {
            uint32_t af[2][4], bf[4][2];
            ldsm4(af[0][0], af[0][1], af[0][2], af[0][3], pstage + ks * 2 + aoff[0]);
            ldsm4(af[1][0], af[1][1], af[1][2], af[1][3], pstage + ks * 2 + aoff[1]);
            ldsm4(bf[0][0], bf[0][1], bf[1][0], bf[1][1], vstage + ks * 2 + boff[0]);
            ldsm4(bf[2][0], bf[2][1], bf[3][0], bf[3][1], vstage + ks * 2 + boff[1]);
#pragma unroll
            for (int mt = 0; mt < 2; mt++)
#pragma unroll
                for (int nt = 0; nt < 4; nt++)
                    mma16(acc[mt][nt], af[mt], bf[nt]);
        }
        __syncthreads();
    }

#pragma unroll
    for (int mt = 0; mt < 2; mt++) {
        const int qrow = qt * 128 + wm * 32 + mt * 16 + g;
#pragma unroll
        for (int nt = 0; nt < 4; nt++) {
            const int cc = h * 64 + wn * 32 + nt * 8 + 2 * tg;
            *(__half2*)(Cout + ((size_t)(b * SS) + qrow) * DD + cc) =
                __floats2half2_rn(acc[mt][nt][0], acc[mt][nt][1]);
            *(__half2*)(Cout + ((size_t)(b * SS) + qrow + 8) * DD + cc) =
                __floats2half2_rn(acc[mt][nt][2], acc[mt][nt][3]);
        }
    }
}

// ---------------- launch ----------------
extern "C" void kernel_launch(void* const* d_in, const int* in_sizes, int n_in,
                              void* d_out, int out_size)
{
    const float* x  = (const float*)d_in[0];
    const float* Wq = (const float*)d_in[1];
    const float* bq = (const float*)d_in[2];
    const float* Wk = (const float*)d_in[3];
    const float* bk = (const float*)d_in[4];
    const float* Wv = (const float*)d_in[5];
    const float* bv = (const float*)d_in[6];
    const float* Wo = (const float*)d_in[7];
    const float* bo = (const float*)d_in[8];

    float* out  = (float*)d_out;
    float* attn = out + (size_t)NR * DD;   // tuple order: (out, attn)

    __half *pW3, *pWo, *pX, *pQKV, *pVT, *pC, *pP16;
    float *pb3;
    cudaGetSymbolAddress((void**)&pW3,  g_W3);
    cudaGetSymbolAddress((void**)&pWo,  g_Wo);
    cudaGetSymbolAddress((void**)&pb3,  g_b3);
    cudaGetSymbolAddress((void**)&pX,   g_X);
    cudaGetSymbolAddress((void**)&pQKV, g_QKV);
    cudaGetSymbolAddress((void**)&pVT,  g_VT);
    cudaGetSymbolAddress((void**)&pC,   g_C);
    cudaGetSymbolAddress((void**)&pP16, g_P16);

    const int gemm_smem   = 4 * HSTG * 2 * 2;              // 81920 B
    const int scores_smem = 2 * 128 * 72 * 2;              // 36864 B
    const int ctx_smem    = (2 * PSTH + 2 * VST) * 2;      // 55296 B
    cudaFuncSetAttribute(gemm_h<true>,  cudaFuncAttributeMaxDynamicSharedMemorySize, gemm_smem);
    cudaFuncSetAttribute(gemm_h<false>, cudaFuncAttributeMaxDynamicSharedMemorySize, gemm_smem);
    cudaFuncSetAttribute(scores_h,      cudaFuncAttributeMaxDynamicSharedMemorySize, scores_smem);
    cudaFuncSetAttribute(ctx_h,         cudaFuncAttributeMaxDynamicSharedMemorySize, ctx_smem);

    // 1) prep
    concat_h<<<(DD * DD / 4) / 256, 256>>>(
        (const float4*)Wq, (const float4*)Wk, (const float4*)Wv, (const float4*)Wo,
        bq, bk, bv);
    roundx_h<<<((size_t)NR * DD / 4) / 256, 256>>>((const float4*)x);

    // 2) fused QKV projection -> fp16
    gemm_h<true><<<dim3(3072 / 128, NR / 128), 256, gemm_smem>>>(pX, pW3, pb3, pQKV, NR, 3072, DD);

    // 3) transpose V slice for ctx B-operand layout
    transpose_v<<<dim3(SS / 64, BB * HH), 256>>>(pQKV, pVT);

    // 4) raw causal scores (fp16 mma) -> attn region fp32
    scores_h<<<dim3(SS / 128, SS / 128, BB * HH), 256, scores_smem>>>(pQKV, attn);

    // 5) softmax per row: fp32 probs to attn + causal-limited fp16 mirror
    softmax_v10<<<BB * HH * SS, 256>>>(attn, pP16);

    // 6) ctx = attn @ V (fp16 mma, fp16 P, full-LDSM) -> fp16 ctx
    ctx_h<<<dim3(SS / 128, BB * HH), 256, ctx_smem>>>(pP16, pVT, pC);

    // 7) output projection (fp32 out)
    gemm_h<false><<<dim3(DD / 128, NR / 128), 256, gemm_smem>>>(pC, pWo, bo, out, NR, DD, DD);
}